// round 1
// baseline (speedup 1.0000x reference)
#include <cuda_runtime.h>
#include <math.h>

// Problem constants
#define BB 8
#define NN 2048
#define DD 256
#define SS 128
#define HH 512
#define EE 1152          // 2H + S
#define BNROWS (BB*NN)   // 16384

#define RSQRT_S 0.08838834764831845f  // 1/sqrt(128)

// ---- scratch (allocation-free rule: __device__ globals) ----
__device__ float d_rowscale[BNROWS];
__device__ float d_u[(size_t)BNROWS*HH];
__device__ float d_v[(size_t)BNROWS*HH];
__device__ float d_qb[(size_t)BNROWS*SS];
__device__ float d_kb[(size_t)BNROWS*SS];
__device__ float d_attn[(size_t)BB*NN*NN];
__device__ float d_gated[(size_t)BNROWS*HH];

// ============================================================
// Stage 1: per-row normalization scale  (folds g):
//   scale = g / max(||x_row||/sqrt(D), eps)
// ============================================================
__global__ void rowscale_kernel(const float* __restrict__ x,
                                const float* __restrict__ g) {
    int row  = blockIdx.x * blockDim.y + threadIdx.y;
    int lane = threadIdx.x;
    const float4* xr = reinterpret_cast<const float4*>(x + (size_t)row * DD);
    float4 a = xr[lane];
    float4 b = xr[lane + 32];
    float s = a.x*a.x + a.y*a.y + a.z*a.z + a.w*a.w
            + b.x*b.x + b.y*b.y + b.z*b.z + b.w*b.w;
    #pragma unroll
    for (int off = 16; off; off >>= 1) s += __shfl_xor_sync(0xffffffffu, s, off);
    if (lane == 0) {
        float norm = sqrtf(s * (1.0f / DD));
        d_rowscale[row] = g[0] / fmaxf(norm, 1e-5f);
    }
}

// ============================================================
// Common SGEMM tile config: BM=BN=128, BK=8, 256 thr, 8x8 microtile
// ============================================================

// Stage 2: uv = silu(xn @ W_uv + b_uv); split into u / v / (q,k)
__global__ void __launch_bounds__(256)
gemm_uv_kernel(const float* __restrict__ X, const float* __restrict__ Wuv,
               const float* __restrict__ buv, const float* __restrict__ gamma,
               const float* __restrict__ beta) {
    __shared__ float As[8][128];
    __shared__ float Bs[8][128];
    const int tid = threadIdx.x;
    const int tx = tid & 15, ty = tid >> 4;
    const int rowBase = blockIdx.y * 128;
    const int colBase = blockIdx.x * 128;

    const int aRow = tid >> 1;
    const int aCol = (tid & 1) * 4;
    const int bRow = tid >> 5;
    const int bCol = (tid & 31) * 4;

    float acc[8][8];
    #pragma unroll
    for (int i = 0; i < 8; i++)
        #pragma unroll
        for (int j = 0; j < 8; j++) acc[i][j] = 0.f;

    const float ascale = d_rowscale[rowBase + aRow];

    for (int kt = 0; kt < DD; kt += 8) {
        float4 av = *reinterpret_cast<const float4*>(
            X + (size_t)(rowBase + aRow) * DD + kt + aCol);
        As[aCol+0][aRow] = av.x * ascale;
        As[aCol+1][aRow] = av.y * ascale;
        As[aCol+2][aRow] = av.z * ascale;
        As[aCol+3][aRow] = av.w * ascale;
        float4 bv = *reinterpret_cast<const float4*>(
            Wuv + (size_t)(kt + bRow) * EE + colBase + bCol);
        *reinterpret_cast<float4*>(&Bs[bRow][bCol]) = bv;
        __syncthreads();
        #pragma unroll
        for (int k = 0; k < 8; k++) {
            float a[8], b[8];
            #pragma unroll
            for (int i = 0; i < 8; i++) a[i] = As[k][ty*8 + i];
            #pragma unroll
            for (int j = 0; j < 8; j++) b[j] = Bs[k][tx*8 + j];
            #pragma unroll
            for (int i = 0; i < 8; i++)
                #pragma unroll
                for (int j = 0; j < 8; j++) acc[i][j] += a[i] * b[j];
        }
        __syncthreads();
    }

    #pragma unroll
    for (int i = 0; i < 8; i++) {
        int r = rowBase + ty*8 + i;
        #pragma unroll
        for (int j = 0; j < 8; j++) {
            int c = colBase + tx*8 + j;
            float val = acc[i][j] + buv[c];
            val = val / (1.0f + __expf(-val));   // silu
            if (c < HH) {
                d_u[(size_t)r*HH + c] = val;
            } else if (c < 2*HH) {
                d_v[(size_t)r*HH + (c - HH)] = val;
            } else {
                int s = c - 2*HH;
                d_qb[(size_t)r*SS + s] = val * gamma[s]      + beta[s];
                d_kb[(size_t)r*SS + s] = val * gamma[SS + s] + beta[SS + s];
            }
        }
    }
}

// Stage 3: attn = relu(q @ k^T * rsqrt(S))^2   (per batch)
__global__ void __launch_bounds__(256)
gemm_qk_kernel() {
    __shared__ float As[8][128];
    __shared__ float Bs[8][128];
    const int tid = threadIdx.x;
    const int tx = tid & 15, ty = tid >> 4;
    const int rowBase = blockIdx.y * 128;   // query rows
    const int colBase = blockIdx.x * 128;   // key rows
    const int b = blockIdx.z;

    const float* q = d_qb + (size_t)b * NN * SS;
    const float* k = d_kb + (size_t)b * NN * SS;

    const int aRow = tid >> 1;
    const int aCol = (tid & 1) * 4;

    float acc[8][8];
    #pragma unroll
    for (int i = 0; i < 8; i++)
        #pragma unroll
        for (int j = 0; j < 8; j++) acc[i][j] = 0.f;

    for (int kt = 0; kt < SS; kt += 8) {
        float4 av = *reinterpret_cast<const float4*>(
            q + (size_t)(rowBase + aRow) * SS + kt + aCol);
        As[aCol+0][aRow] = av.x;
        As[aCol+1][aRow] = av.y;
        As[aCol+2][aRow] = av.z;
        As[aCol+3][aRow] = av.w;
        // B tile: k[colBase+nn][kt+ss], transpose into Bs[ss][nn]
        float4 bv = *reinterpret_cast<const float4*>(
            k + (size_t)(colBase + aRow) * SS + kt + aCol);
        Bs[aCol+0][aRow] = bv.x;
        Bs[aCol+1][aRow] = bv.y;
        Bs[aCol+2][aRow] = bv.z;
        Bs[aCol+3][aRow] = bv.w;
        __syncthreads();
        #pragma unroll
        for (int kk = 0; kk < 8; kk++) {
            float a[8], bb[8];
            #pragma unroll
            for (int i = 0; i < 8; i++) a[i]  = As[kk][ty*8 + i];
            #pragma unroll
            for (int j = 0; j < 8; j++) bb[j] = Bs[kk][tx*8 + j];
            #pragma unroll
            for (int i = 0; i < 8; i++)
                #pragma unroll
                for (int j = 0; j < 8; j++) acc[i][j] += a[i] * bb[j];
        }
        __syncthreads();
    }

    float* attn = d_attn + (size_t)b * NN * NN;
    #pragma unroll
    for (int i = 0; i < 8; i++) {
        int r = rowBase + ty*8 + i;
        #pragma unroll
        for (int j = 0; j < 8; j++) {
            int c = colBase + tx*8 + j;
            float val = acc[i][j] * RSQRT_S;
            float rel = fmaxf(val, 0.0f);
            attn[(size_t)r * NN + c] = rel * rel;
        }
    }
}

// Stage 4: gated = u * (attn @ v)   (per batch)
__global__ void __launch_bounds__(256)
gemm_av_kernel() {
    __shared__ float As[8][128];
    __shared__ float Bs[8][128];
    const int tid = threadIdx.x;
    const int tx = tid & 15, ty = tid >> 4;
    const int rowBase = blockIdx.y * 128;   // query rows (within batch)
    const int colBase = blockIdx.x * 128;   // H columns
    const int b = blockIdx.z;

    const float* A = d_attn + (size_t)b * NN * NN;
    const float* V = d_v    + (size_t)b * NN * HH;

    const int aRow = tid >> 1;
    const int aCol = (tid & 1) * 4;
    const int bRow = tid >> 5;
    const int bCol = (tid & 31) * 4;

    float acc[8][8];
    #pragma unroll
    for (int i = 0; i < 8; i++)
        #pragma unroll
        for (int j = 0; j < 8; j++) acc[i][j] = 0.f;

    for (int kt = 0; kt < NN; kt += 8) {
        float4 av = *reinterpret_cast<const float4*>(
            A + (size_t)(rowBase + aRow) * NN + kt + aCol);
        As[aCol+0][aRow] = av.x;
        As[aCol+1][aRow] = av.y;
        As[aCol+2][aRow] = av.z;
        As[aCol+3][aRow] = av.w;
        float4 bv = *reinterpret_cast<const float4*>(
            V + (size_t)(kt + bRow) * HH + colBase + bCol);
        *reinterpret_cast<float4*>(&Bs[bRow][bCol]) = bv;
        __syncthreads();
        #pragma unroll
        for (int kk = 0; kk < 8; kk++) {
            float a[8], bb[8];
            #pragma unroll
            for (int i = 0; i < 8; i++) a[i]  = As[kk][ty*8 + i];
            #pragma unroll
            for (int j = 0; j < 8; j++) bb[j] = Bs[kk][tx*8 + j];
            #pragma unroll
            for (int i = 0; i < 8; i++)
                #pragma unroll
                for (int j = 0; j < 8; j++) acc[i][j] += a[i] * bb[j];
        }
        __syncthreads();
    }

    #pragma unroll
    for (int i = 0; i < 8; i++) {
        int rg = b * NN + rowBase + ty*8 + i;   // global row
        #pragma unroll
        for (int j = 0; j < 8; j++) {
            int c = colBase + tx*8 + j;
            d_gated[(size_t)rg*HH + c] = d_u[(size_t)rg*HH + c] * acc[i][j];
        }
    }
}

// Stage 5: out = gated @ W_o + b_o
__global__ void __launch_bounds__(256)
gemm_o_kernel(const float* __restrict__ Wo, const float* __restrict__ bo,
              float* __restrict__ out) {
    __shared__ float As[8][128];
    __shared__ float Bs[8][128];
    const int tid = threadIdx.x;
    const int tx = tid & 15, ty = tid >> 4;
    const int rowBase = blockIdx.y * 128;
    const int colBase = blockIdx.x * 128;

    const int aRow = tid >> 1;
    const int aCol = (tid & 1) * 4;
    const int bRow = tid >> 5;
    const int bCol = (tid & 31) * 4;

    float acc[8][8];
    #pragma unroll
    for (int i = 0; i < 8; i++)
        #pragma unroll
        for (int j = 0; j < 8; j++) acc[i][j] = 0.f;

    for (int kt = 0; kt < HH; kt += 8) {
        float4 av = *reinterpret_cast<const float4*>(
            d_gated + (size_t)(rowBase + aRow) * HH + kt + aCol);
        As[aCol+0][aRow] = av.x;
        As[aCol+1][aRow] = av.y;
        As[aCol+2][aRow] = av.z;
        As[aCol+3][aRow] = av.w;
        float4 bv = *reinterpret_cast<const float4*>(
            Wo + (size_t)(kt + bRow) * DD + colBase + bCol);
        *reinterpret_cast<float4*>(&Bs[bRow][bCol]) = bv;
        __syncthreads();
        #pragma unroll
        for (int kk = 0; kk < 8; kk++) {
            float a[8], bb[8];
            #pragma unroll
            for (int i = 0; i < 8; i++) a[i]  = As[kk][ty*8 + i];
            #pragma unroll
            for (int j = 0; j < 8; j++) bb[j] = Bs[kk][tx*8 + j];
            #pragma unroll
            for (int i = 0; i < 8; i++)
                #pragma unroll
                for (int j = 0; j < 8; j++) acc[i][j] += a[i] * bb[j];
        }
        __syncthreads();
    }

    #pragma unroll
    for (int i = 0; i < 8; i++) {
        int r = rowBase + ty*8 + i;
        #pragma unroll
        for (int j = 0; j < 8; j++) {
            int c = colBase + tx*8 + j;
            out[(size_t)r*DD + c] = acc[i][j] + bo[c];
        }
    }
}

// ============================================================
extern "C" void kernel_launch(void* const* d_in, const int* in_sizes, int n_in,
                              void* d_out, int out_size) {
    (void)in_sizes; (void)n_in; (void)out_size;
    const float* x     = (const float*)d_in[0];
    const float* g     = (const float*)d_in[1];
    const float* Wuv   = (const float*)d_in[2];
    const float* buv   = (const float*)d_in[3];
    const float* gamma = (const float*)d_in[4];
    const float* beta  = (const float*)d_in[5];
    const float* Wo    = (const float*)d_in[6];
    const float* bo    = (const float*)d_in[7];
    float* out = (float*)d_out;

    rowscale_kernel<<<BNROWS/8, dim3(32, 8)>>>(x, g);
    gemm_uv_kernel<<<dim3(EE/128, BNROWS/128), 256>>>(x, Wuv, buv, gamma, beta);
    gemm_qk_kernel<<<dim3(NN/128, NN/128, BB), 256>>>();
    gemm_av_kernel<<<dim3(HH/128, NN/128, BB), 256>>>();
    gemm_o_kernel<<<dim3(DD/128, BNROWS/128), 256>>>(Wo, bo, out);
}

// round 3
// speedup vs baseline: 2.5596x; 2.5596x over previous
#include <cuda_runtime.h>
#include <cuda_bf16.h>
#include <cstdint>
#include <math.h>

// Problem constants
#define BB 8
#define NN 2048
#define DD 256
#define SS 128
#define HH 512
#define EE 1152          // 2H + S
#define BNROWS (BB*NN)   // 16384
#define RSQRT_S 0.08838834764831845f  // 1/sqrt(128)

// ---- scratch (allocation-free rule: __device__ globals) ----
__device__ __nv_bfloat16 d_xhi[(size_t)BNROWS*DD];
__device__ __nv_bfloat16 d_xlo[(size_t)BNROWS*DD];
__device__ float d_u[(size_t)BNROWS*HH];
__device__ float d_v[(size_t)BNROWS*HH];
__device__ __nv_bfloat16 d_qhi[(size_t)BNROWS*SS];
__device__ __nv_bfloat16 d_qlo[(size_t)BNROWS*SS];
__device__ __nv_bfloat16 d_khi[(size_t)BNROWS*SS];
__device__ __nv_bfloat16 d_klo[(size_t)BNROWS*SS];
__device__ __nv_bfloat16 d_vThi[(size_t)BB*HH*NN];   // [b][h][m]
__device__ __nv_bfloat16 d_vTlo[(size_t)BB*HH*NN];
__device__ __nv_bfloat16 d_ahi[(size_t)BB*NN*NN];    // attn [b][n][m]
__device__ __nv_bfloat16 d_alo[(size_t)BB*NN*NN];
__device__ __nv_bfloat16 d_ghi[(size_t)BNROWS*HH];   // gated hi/lo
__device__ __nv_bfloat16 d_glo[(size_t)BNROWS*HH];
__device__ __nv_bfloat16 d_wuvThi[(size_t)EE*DD];    // W_uv^T [e][d]
__device__ __nv_bfloat16 d_wuvTlo[(size_t)EE*DD];
__device__ __nv_bfloat16 d_woThi[(size_t)DD*HH];     // W_o^T [d][h]
__device__ __nv_bfloat16 d_woTlo[(size_t)DD*HH];

// ============================================================
// Helpers
// ============================================================
__device__ __forceinline__ uint32_t smem_u32(const void* p) {
    uint32_t a;
    asm("{ .reg .u64 t; cvta.to.shared.u64 t, %1; cvt.u32.u64 %0, t; }"
        : "=r"(a) : "l"(p));
    return a;
}

#define LDSM_X4(r0, r1, r2, r3, addr) \
    asm volatile("ldmatrix.sync.aligned.m8n8.x4.shared.b16 {%0,%1,%2,%3}, [%4];" \
        : "=r"(r0), "=r"(r1), "=r"(r2), "=r"(r3) : "r"(addr))

#define MMA16816(d, a, b) \
    asm volatile("mma.sync.aligned.m16n8k16.row.col.f32.bf16.bf16.f32 " \
        "{%0,%1,%2,%3}, {%4,%5,%6,%7}, {%8,%9}, {%0,%1,%2,%3};" \
        : "+f"((d)[0]), "+f"((d)[1]), "+f"((d)[2]), "+f"((d)[3]) \
        : "r"((a)[0]), "r"((a)[1]), "r"((a)[2]), "r"((a)[3]), \
          "r"((b)[0]), "r"((b)[1]))

__device__ __forceinline__ void cp16(uint32_t dst, const __nv_bfloat16* src) {
    asm volatile("cp.async.cg.shared.global [%0], [%1], 16;"
        :: "r"(dst), "l"(src));
}
#define CP_COMMIT() asm volatile("cp.async.commit_group;" ::: "memory")
#define CP_WAIT1()  asm volatile("cp.async.wait_group 1;" ::: "memory")
#define CP_WAIT0()  asm volatile("cp.async.wait_group 0;" ::: "memory")

__device__ __forceinline__ void bf16split(float v, __nv_bfloat16& hi, __nv_bfloat16& lo) {
    hi = __float2bfloat16(v);
    lo = __float2bfloat16(v - __bfloat162float(hi));
}

// ============================================================
// Shared HMMA GEMM core: BM=128, BN=128, BK=64, 256 threads.
// A row-major [128][K], B n-major [128][K], both as hi/lo bf16.
// 3-term split accumulation into fp32.
// smem per stage 64KB (Ah 16K | Al 16K | Bh 16K | Bl 16K), 2 stages.
// ============================================================
#define STAGE_BYTES 65536
#define MMA_SMEM    (2*STAGE_BYTES)

__device__ __forceinline__ void load_oper(uint32_t dstBase, const __nv_bfloat16* src,
                                          int ld, int kt, int tid) {
    #pragma unroll
    for (int j = 0; j < 4; j++) {
        int g = tid + j * 256;        // 1024 granules of 16B = 128 rows x 8
        int row = g >> 3;
        int gi  = g & 7;
        int gis = gi ^ (row & 7);
        cp16(dstBase + row * 128 + gis * 16, src + (size_t)row * ld + kt + gi * 8);
    }
}

__device__ __forceinline__ void load_chunk(uint32_t sb, int stage,
        const __nv_bfloat16* Ah, const __nv_bfloat16* Al, int ldA,
        const __nv_bfloat16* Bh, const __nv_bfloat16* Bl, int ldB,
        int kt, int tid) {
    uint32_t st = sb + stage * STAGE_BYTES;
    load_oper(st,         Ah, ldA, kt, tid);
    load_oper(st + 16384, Al, ldA, kt, tid);
    load_oper(st + 32768, Bh, ldB, kt, tid);
    load_oper(st + 49152, Bl, ldB, kt, tid);
}

__device__ __forceinline__ void compute_chunk(uint32_t st, int lane, int wm, int wn,
                                              float acc[4][4][4]) {
    const uint32_t aH = st, aL = st + 16384, bH = st + 32768, bL = st + 49152;
    #pragma unroll
    for (int ks = 0; ks < 4; ks++) {
        uint32_t Ahf[4][4], Alf[4][4];
        #pragma unroll
        for (int mi = 0; mi < 4; mi++) {
            int row = wm * 64 + mi * 16 + (lane & 15);
            int gi  = ks * 2 + (lane >> 4);
            uint32_t off = row * 128 + (gi ^ (row & 7)) * 16;
            LDSM_X4(Ahf[mi][0], Ahf[mi][1], Ahf[mi][2], Ahf[mi][3], aH + off);
            LDSM_X4(Alf[mi][0], Alf[mi][1], Alf[mi][2], Alf[mi][3], aL + off);
        }
        uint32_t Bhf[4][2], Blf[4][2];
        #pragma unroll
        for (int np = 0; np < 2; np++) {
            int row = wn * 32 + np * 16 + (lane & 7) + ((lane >> 4) << 3);
            int gi  = ks * 2 + ((lane >> 3) & 1);
            uint32_t off = row * 128 + (gi ^ (row & 7)) * 16;
            LDSM_X4(Bhf[2*np][0], Bhf[2*np][1], Bhf[2*np+1][0], Bhf[2*np+1][1], bH + off);
            LDSM_X4(Blf[2*np][0], Blf[2*np][1], Blf[2*np+1][0], Blf[2*np+1][1], bL + off);
        }
        #pragma unroll
        for (int mi = 0; mi < 4; mi++)
            #pragma unroll
            for (int ni = 0; ni < 4; ni++) {
                MMA16816(acc[mi][ni], Ahf[mi], Bhf[ni]);
                MMA16816(acc[mi][ni], Ahf[mi], Blf[ni]);
                MMA16816(acc[mi][ni], Alf[mi], Bhf[ni]);
            }
    }
}

template <class Epi>
__device__ __forceinline__ void mma_gemm_core(
        const __nv_bfloat16* Ah, const __nv_bfloat16* Al, int ldA,
        const __nv_bfloat16* Bh, const __nv_bfloat16* Bl, int ldB,
        int K, char* smem, Epi epi) {
    uint32_t sb = smem_u32(smem);
    int tid = threadIdx.x;
    int lane = tid & 31, warp = tid >> 5;
    int wm = warp & 1, wn = warp >> 1;

    float acc[4][4][4] = {};
    const int nc = K / 64;

    load_chunk(sb, 0, Ah, Al, ldA, Bh, Bl, ldB, 0, tid);
    CP_COMMIT();
    for (int c = 0; c < nc; c++) {
        if (c + 1 < nc) {
            load_chunk(sb, (c + 1) & 1, Ah, Al, ldA, Bh, Bl, ldB, (c + 1) * 64, tid);
            CP_COMMIT();
            CP_WAIT1();
        } else {
            CP_WAIT0();
        }
        __syncthreads();
        compute_chunk(sb + (c & 1) * STAGE_BYTES, lane, wm, wn, acc);
        __syncthreads();
    }

    #pragma unroll
    for (int mi = 0; mi < 4; mi++)
        #pragma unroll
        for (int ni = 0; ni < 4; ni++) {
            int r = wm * 64 + mi * 16 + (lane >> 2);
            int c = wn * 32 + ni * 8 + (lane & 3) * 2;
            epi(r,     c, acc[mi][ni][0], acc[mi][ni][1]);
            epi(r + 8, c, acc[mi][ni][2], acc[mi][ni][3]);
        }
}

// ============================================================
// prep: x -> normalized hi/lo bf16
// ============================================================
__global__ void prep_x_kernel(const float* __restrict__ x,
                              const float* __restrict__ g) {
    int row  = blockIdx.x * blockDim.y + threadIdx.y;
    int lane = threadIdx.x;
    const float4* xr = reinterpret_cast<const float4*>(x + (size_t)row * DD);
    float4 a = xr[lane];
    float4 b = xr[lane + 32];
    float s = a.x*a.x + a.y*a.y + a.z*a.z + a.w*a.w
            + b.x*b.x + b.y*b.y + b.z*b.z + b.w*b.w;
    #pragma unroll
    for (int off = 16; off; off >>= 1) s += __shfl_xor_sync(0xffffffffu, s, off);
    s = __shfl_sync(0xffffffffu, s, 0);
    float norm = sqrtf(s * (1.0f / DD));
    float scale = g[0] / fmaxf(norm, 1e-5f);

    float va[8] = {a.x, a.y, a.z, a.w, b.x, b.y, b.z, b.w};
    int idx[2] = {lane * 4, 128 + lane * 4};
    #pragma unroll
    for (int h = 0; h < 2; h++)
        #pragma unroll
        for (int j = 0; j < 4; j++) {
            float v = va[h*4 + j] * scale;
            __nv_bfloat16 hi, lo;
            bf16split(v, hi, lo);
            d_xhi[(size_t)row*DD + idx[h] + j] = hi;
            d_xlo[(size_t)row*DD + idx[h] + j] = lo;
        }
}

// ============================================================
// generic transpose + split:  in [R][C] fp32 -> out [C][R] bf16 hi/lo
// grid (C/32, R/32, batches), block (32, 8)
// ============================================================
__global__ void transpose_split_kernel(const float* __restrict__ in,
                                       __nv_bfloat16* __restrict__ outh,
                                       __nv_bfloat16* __restrict__ outl,
                                       int R, int C) {
    __shared__ float t[32][33];
    size_t boff = (size_t)blockIdx.z * R * C;
    int c0 = blockIdx.x * 32, r0 = blockIdx.y * 32;
    int tx = threadIdx.x, ty = threadIdx.y;
    #pragma unroll
    for (int i = ty; i < 32; i += 8)
        t[i][tx] = in[boff + (size_t)(r0 + i) * C + c0 + tx];
    __syncthreads();
    #pragma unroll
    for (int i = ty; i < 32; i += 8) {
        float val = t[tx][i];   // = in[r0+tx][c0+i]
        __nv_bfloat16 hi, lo;
        bf16split(val, hi, lo);
        size_t idx = boff + (size_t)(c0 + i) * R + r0 + tx;
        outh[idx] = hi;
        outl[idx] = lo;
    }
}

// ============================================================
// Epilogues
// ============================================================
struct EpiUV {
    int rowBase, colBase;
    const float *buv, *gamma, *beta;
    __device__ void operator()(int r, int c, float v0, float v1) const {
        int row = rowBase + r;
        float vv[2] = {v0, v1};
        #pragma unroll
        for (int i = 0; i < 2; i++) {
            int col = colBase + c + i;
            float val = vv[i] + buv[col];
            val = val / (1.0f + __expf(-val));
            if (col < HH) {
                d_u[(size_t)row*HH + col] = val;
            } else if (col < 2*HH) {
                d_v[(size_t)row*HH + (col - HH)] = val;
            } else {
                int s = col - 2*HH;
                float vq = val * gamma[s]      + beta[s];
                float vk = val * gamma[SS + s] + beta[SS + s];
                size_t qi = (size_t)row*SS + s;
                __nv_bfloat16 hi, lo;
                bf16split(vq, hi, lo); d_qhi[qi] = hi; d_qlo[qi] = lo;
                bf16split(vk, hi, lo); d_khi[qi] = hi; d_klo[qi] = lo;
            }
        }
    }
};

struct EpiQK {
    size_t rowOff;   // b*NN + rowBase
    int colBase;
    __device__ void operator()(int r, int c, float v0, float v1) const {
        size_t idx = (rowOff + r) * NN + colBase + c;
        float a0 = fmaxf(v0 * RSQRT_S, 0.0f); a0 *= a0;
        float a1 = fmaxf(v1 * RSQRT_S, 0.0f); a1 *= a1;
        __nv_bfloat16 h0, l0, h1, l1;
        bf16split(a0, h0, l0);
        bf16split(a1, h1, l1);
        *reinterpret_cast<__nv_bfloat162*>(d_ahi + idx) = __nv_bfloat162{h0, h1};
        *reinterpret_cast<__nv_bfloat162*>(d_alo + idx) = __nv_bfloat162{l0, l1};
    }
};

struct EpiAV {
    size_t rowOff;   // b*NN + rowBase
    int colBase;
    __device__ void operator()(int r, int c, float v0, float v1) const {
        size_t rg = rowOff + r;
        size_t idx = rg * HH + colBase + c;
        float2 uu = *reinterpret_cast<const float2*>(d_u + idx);
        float g0 = uu.x * v0, g1 = uu.y * v1;
        __nv_bfloat16 h0, l0, h1, l1;
        bf16split(g0, h0, l0);
        bf16split(g1, h1, l1);
        *reinterpret_cast<__nv_bfloat162*>(d_ghi + idx) = __nv_bfloat162{h0, h1};
        *reinterpret_cast<__nv_bfloat162*>(d_glo + idx) = __nv_bfloat162{l0, l1};
    }
};

struct EpiO {
    int rowBase, colBase;
    const float* bo;
    float* out;
    __device__ void operator()(int r, int c, float v0, float v1) const {
        int row = rowBase + r;
        int col = colBase + c;
        float2 o = {v0 + bo[col], v1 + bo[col + 1]};
        *reinterpret_cast<float2*>(out + (size_t)row*DD + col) = o;
    }
};

// ============================================================
// GEMM kernels
// ============================================================
__global__ void __launch_bounds__(256)
k_uv(const float* __restrict__ buv, const float* __restrict__ gamma,
     const float* __restrict__ beta) {
    extern __shared__ char smem[];
    int rowBase = blockIdx.y * 128, colBase = blockIdx.x * 128;
    EpiUV epi{rowBase, colBase, buv, gamma, beta};
    mma_gemm_core(d_xhi + (size_t)rowBase * DD, d_xlo + (size_t)rowBase * DD, DD,
                  d_wuvThi + (size_t)colBase * DD, d_wuvTlo + (size_t)colBase * DD, DD,
                  DD, smem, epi);
}

__global__ void __launch_bounds__(256)
k_qk() {
    extern __shared__ char smem[];
    int b = blockIdx.z, rowBase = blockIdx.y * 128, colBase = blockIdx.x * 128;
    size_t ra = (size_t)b * NN + rowBase;
    size_t rb = (size_t)b * NN + colBase;
    EpiQK epi{ra, colBase};
    mma_gemm_core(d_qhi + ra * SS, d_qlo + ra * SS, SS,
                  d_khi + rb * SS, d_klo + rb * SS, SS,
                  SS, smem, epi);
}

__global__ void __launch_bounds__(256)
k_av() {
    extern __shared__ char smem[];
    int b = blockIdx.z, rowBase = blockIdx.y * 128, colBase = blockIdx.x * 128;
    size_t ra = (size_t)b * NN + rowBase;
    size_t hb = (size_t)b * HH + colBase;
    EpiAV epi{ra, colBase};
    mma_gemm_core(d_ahi + ra * NN, d_alo + ra * NN, NN,
                  d_vThi + hb * NN, d_vTlo + hb * NN, NN,
                  NN, smem, epi);
}

__global__ void __launch_bounds__(256)
k_o(const float* __restrict__ bo, float* __restrict__ out) {
    extern __shared__ char smem[];
    int rowBase = blockIdx.y * 128, colBase = blockIdx.x * 128;
    EpiO epi{rowBase, colBase, bo, out};
    mma_gemm_core(d_ghi + (size_t)rowBase * HH, d_glo + (size_t)rowBase * HH, HH,
                  d_woThi + (size_t)colBase * HH, d_woTlo + (size_t)colBase * HH, HH,
                  HH, smem, epi);
}

// ============================================================
extern "C" void kernel_launch(void* const* d_in, const int* in_sizes, int n_in,
                              void* d_out, int out_size) {
    (void)in_sizes; (void)n_in; (void)out_size;
    const float* x     = (const float*)d_in[0];
    const float* g     = (const float*)d_in[1];
    const float* Wuv   = (const float*)d_in[2];
    const float* buv   = (const float*)d_in[3];
    const float* gamma = (const float*)d_in[4];
    const float* beta  = (const float*)d_in[5];
    const float* Wo    = (const float*)d_in[6];
    const float* bo    = (const float*)d_in[7];
    float* out = (float*)d_out;

    static int smem_set = 0;
    if (!smem_set) {
        cudaFuncSetAttribute(k_uv, cudaFuncAttributeMaxDynamicSharedMemorySize, MMA_SMEM);
        cudaFuncSetAttribute(k_qk, cudaFuncAttributeMaxDynamicSharedMemorySize, MMA_SMEM);
        cudaFuncSetAttribute(k_av, cudaFuncAttributeMaxDynamicSharedMemorySize, MMA_SMEM);
        cudaFuncSetAttribute(k_o,  cudaFuncAttributeMaxDynamicSharedMemorySize, MMA_SMEM);
        smem_set = 1;
    }

    // scratch pointers for transpose_split of v (device symbols usable directly
    // in kernels; here we need raw pointers as args)
    // prep
    prep_x_kernel<<<BNROWS/8, dim3(32, 8)>>>(x, g);

    {   // W_uv: [D=256][E=1152] -> [E][D]
        __nv_bfloat16 *th, *tl;
        cudaGetSymbolAddress((void**)&th, d_wuvThi);
        cudaGetSymbolAddress((void**)&tl, d_wuvTlo);
        transpose_split_kernel<<<dim3(EE/32, DD/32, 1), dim3(32, 8)>>>(Wuv, th, tl, DD, EE);
    }
    {   // W_o: [H=512][D=256] -> [D][H]
        __nv_bfloat16 *th, *tl;
        cudaGetSymbolAddress((void**)&th, d_woThi);
        cudaGetSymbolAddress((void**)&tl, d_woTlo);
        transpose_split_kernel<<<dim3(DD/32, HH/32, 1), dim3(32, 8)>>>(Wo, th, tl, HH, DD);
    }

    k_uv<<<dim3(EE/128, BNROWS/128), 256, MMA_SMEM>>>(buv, gamma, beta);

    {   // v: per-batch [N=2048][H=512] -> [H][N]
        float* vin;
        __nv_bfloat16 *th, *tl;
        cudaGetSymbolAddress((void**)&vin, d_v);
        cudaGetSymbolAddress((void**)&th, d_vThi);
        cudaGetSymbolAddress((void**)&tl, d_vTlo);
        transpose_split_kernel<<<dim3(HH/32, NN/32, BB), dim3(32, 8)>>>(vin, th, tl, NN, HH);
    }

    k_qk<<<dim3(NN/128, NN/128, BB), 256, MMA_SMEM>>>();
    k_av<<<dim3(HH/128, NN/128, BB), 256, MMA_SMEM>>>();
    k_o<<<dim3(DD/128, BNROWS/128), 256, MMA_SMEM>>>(bo, out);
}

// round 4
// speedup vs baseline: 3.1583x; 1.2339x over previous
#include <cuda_runtime.h>
#include <cuda_bf16.h>
#include <cstdint>
#include <math.h>

// Problem constants
#define BB 8
#define NN 2048
#define DD 256
#define SS 128
#define HH 512
#define EE 1152          // 2H + S
#define BNROWS (BB*NN)   // 16384
#define RSQRT_S 0.08838834764831845f  // 1/sqrt(128)

// ---- scratch (allocation-free rule: __device__ globals) ----
__device__ __nv_bfloat16 d_xhi[(size_t)BNROWS*DD];
__device__ __nv_bfloat16 d_xlo[(size_t)BNROWS*DD];
__device__ float d_u[(size_t)BNROWS*HH];
__device__ float d_v[(size_t)BNROWS*HH];
__device__ __nv_bfloat16 d_qhi[(size_t)BNROWS*SS];
__device__ __nv_bfloat16 d_qlo[(size_t)BNROWS*SS];
__device__ __nv_bfloat16 d_khi[(size_t)BNROWS*SS];
__device__ __nv_bfloat16 d_klo[(size_t)BNROWS*SS];
__device__ __nv_bfloat16 d_vThi[(size_t)BB*HH*NN];   // [b][h][m]
__device__ __nv_bfloat16 d_vTlo[(size_t)BB*HH*NN];
__device__ __nv_bfloat16 d_ahi[(size_t)BB*NN*NN];    // attn [b][n][m]
__device__ __nv_bfloat16 d_alo[(size_t)BB*NN*NN];
__device__ __nv_bfloat16 d_ghi[(size_t)BNROWS*HH];   // gated hi/lo
__device__ __nv_bfloat16 d_glo[(size_t)BNROWS*HH];
__device__ __nv_bfloat16 d_wuvThi[(size_t)EE*DD];    // W_uv^T [e][d]
__device__ __nv_bfloat16 d_wuvTlo[(size_t)EE*DD];
__device__ __nv_bfloat16 d_woThi[(size_t)DD*HH];     // W_o^T [d][h]
__device__ __nv_bfloat16 d_woTlo[(size_t)DD*HH];

// ============================================================
// Helpers
// ============================================================
__device__ __forceinline__ uint32_t smem_u32(const void* p) {
    uint32_t a;
    asm("{ .reg .u64 t; cvta.to.shared.u64 t, %1; cvt.u32.u64 %0, t; }"
        : "=r"(a) : "l"(p));
    return a;
}

#define LDSM_X4(r0, r1, r2, r3, addr) \
    asm volatile("ldmatrix.sync.aligned.m8n8.x4.shared.b16 {%0,%1,%2,%3}, [%4];" \
        : "=r"(r0), "=r"(r1), "=r"(r2), "=r"(r3) : "r"(addr))

#define MMA16816(d, a, b) \
    asm volatile("mma.sync.aligned.m16n8k16.row.col.f32.bf16.bf16.f32 " \
        "{%0,%1,%2,%3}, {%4,%5,%6,%7}, {%8,%9}, {%0,%1,%2,%3};" \
        : "+f"((d)[0]), "+f"((d)[1]), "+f"((d)[2]), "+f"((d)[3]) \
        : "r"((a)[0]), "r"((a)[1]), "r"((a)[2]), "r"((a)[3]), \
          "r"((b)[0]), "r"((b)[1]))

__device__ __forceinline__ void cp16(uint32_t dst, const __nv_bfloat16* src) {
    asm volatile("cp.async.cg.shared.global [%0], [%1], 16;"
        :: "r"(dst), "l"(src));
}
#define CP_COMMIT() asm volatile("cp.async.commit_group;" ::: "memory")
#define CP_WAIT1()  asm volatile("cp.async.wait_group 1;" ::: "memory")
#define CP_WAIT0()  asm volatile("cp.async.wait_group 0;" ::: "memory")

__device__ __forceinline__ void bf16split(float v, __nv_bfloat16& hi, __nv_bfloat16& lo) {
    hi = __float2bfloat16(v);
    lo = __float2bfloat16(v - __bfloat162float(hi));
}

// ============================================================
// Shared HMMA GEMM core: BM=128, BN=64, BK=64, 256 threads, 2 CTAs/SM.
// A row-major [128][K], B n-major [64][K], both hi/lo bf16, 3-term split.
// stage = Ah 16K | Al 16K | Bh 8K | Bl 8K = 48KB, double-buffered (96KB).
// ============================================================
#define STAGE_BYTES 49152
#define MMA_SMEM    (2*STAGE_BYTES)

// ROWS*8 granules of 16B, strided by 256 threads
template <int ROWS>
__device__ __forceinline__ void load_oper(uint32_t dstBase, const __nv_bfloat16* src,
                                          int ld, int kt, int tid) {
    #pragma unroll
    for (int j = 0; j < ROWS*8/256; j++) {
        int g = tid + j * 256;
        int row = g >> 3;
        int gi  = g & 7;
        int gis = gi ^ (row & 7);
        cp16(dstBase + row * 128 + gis * 16, src + (size_t)row * ld + kt + gi * 8);
    }
}

__device__ __forceinline__ void load_chunk(uint32_t sb, int stage,
        const __nv_bfloat16* Ah, const __nv_bfloat16* Al, int ldA,
        const __nv_bfloat16* Bh, const __nv_bfloat16* Bl, int ldB,
        int kt, int tid) {
    uint32_t st = sb + stage * STAGE_BYTES;
    load_oper<128>(st,         Ah, ldA, kt, tid);
    load_oper<128>(st + 16384, Al, ldA, kt, tid);
    load_oper<64> (st + 32768, Bh, ldB, kt, tid);
    load_oper<64> (st + 40960, Bl, ldB, kt, tid);
}

__device__ __forceinline__ void compute_chunk(uint32_t st, int lane, int wm, int wn,
                                              float acc[4][2][4]) {
    const uint32_t aH = st, aL = st + 16384, bH = st + 32768, bL = st + 40960;
    #pragma unroll
    for (int ks = 0; ks < 4; ks++) {
        uint32_t Ahf[4][4], Alf[4][4];
        #pragma unroll
        for (int mi = 0; mi < 4; mi++) {
            int row = wm * 64 + mi * 16 + (lane & 15);
            int gi  = ks * 2 + (lane >> 4);
            uint32_t off = row * 128 + (gi ^ (row & 7)) * 16;
            LDSM_X4(Ahf[mi][0], Ahf[mi][1], Ahf[mi][2], Ahf[mi][3], aH + off);
            LDSM_X4(Alf[mi][0], Alf[mi][1], Alf[mi][2], Alf[mi][3], aL + off);
        }
        uint32_t Bhf[2][2], Blf[2][2];
        {
            int row = wn * 16 + (lane & 7) + ((lane >> 4) << 3);
            int gi  = ks * 2 + ((lane >> 3) & 1);
            uint32_t off = row * 128 + (gi ^ (row & 7)) * 16;
            LDSM_X4(Bhf[0][0], Bhf[0][1], Bhf[1][0], Bhf[1][1], bH + off);
            LDSM_X4(Blf[0][0], Blf[0][1], Blf[1][0], Blf[1][1], bL + off);
        }
        #pragma unroll
        for (int mi = 0; mi < 4; mi++)
            #pragma unroll
            for (int ni = 0; ni < 2; ni++) {
                MMA16816(acc[mi][ni], Ahf[mi], Bhf[ni]);
                MMA16816(acc[mi][ni], Ahf[mi], Blf[ni]);
                MMA16816(acc[mi][ni], Alf[mi], Bhf[ni]);
            }
    }
}

template <class Epi>
__device__ __forceinline__ void mma_gemm_core(
        const __nv_bfloat16* Ah, const __nv_bfloat16* Al, int ldA,
        const __nv_bfloat16* Bh, const __nv_bfloat16* Bl, int ldB,
        int K, char* smem, Epi epi) {
    uint32_t sb = smem_u32(smem);
    int tid = threadIdx.x;
    int lane = tid & 31, warp = tid >> 5;
    int wm = warp & 1, wn = warp >> 1;

    float acc[4][2][4] = {};
    const int nc = K / 64;

    load_chunk(sb, 0, Ah, Al, ldA, Bh, Bl, ldB, 0, tid);
    CP_COMMIT();
    for (int c = 0; c < nc; c++) {
        if (c + 1 < nc) {
            load_chunk(sb, (c + 1) & 1, Ah, Al, ldA, Bh, Bl, ldB, (c + 1) * 64, tid);
            CP_COMMIT();
            CP_WAIT1();
        } else {
            CP_WAIT0();
        }
        __syncthreads();
        compute_chunk(sb + (c & 1) * STAGE_BYTES, lane, wm, wn, acc);
        __syncthreads();
    }

    #pragma unroll
    for (int mi = 0; mi < 4; mi++)
        #pragma unroll
        for (int ni = 0; ni < 2; ni++) {
            int r = wm * 64 + mi * 16 + (lane >> 2);
            int c = wn * 16 + ni * 8 + (lane & 3) * 2;
            epi(r,     c, acc[mi][ni][0], acc[mi][ni][1]);
            epi(r + 8, c, acc[mi][ni][2], acc[mi][ni][3]);
        }
}

// ============================================================
// prep: x -> normalized hi/lo bf16
// ============================================================
__global__ void prep_x_kernel(const float* __restrict__ x,
                              const float* __restrict__ g) {
    int row  = blockIdx.x * blockDim.y + threadIdx.y;
    int lane = threadIdx.x;
    const float4* xr = reinterpret_cast<const float4*>(x + (size_t)row * DD);
    float4 a = xr[lane];
    float4 b = xr[lane + 32];
    float s = a.x*a.x + a.y*a.y + a.z*a.z + a.w*a.w
            + b.x*b.x + b.y*b.y + b.z*b.z + b.w*b.w;
    #pragma unroll
    for (int off = 16; off; off >>= 1) s += __shfl_xor_sync(0xffffffffu, s, off);
    s = __shfl_sync(0xffffffffu, s, 0);
    float norm = sqrtf(s * (1.0f / DD));
    float scale = g[0] / fmaxf(norm, 1e-5f);

    float va[8] = {a.x, a.y, a.z, a.w, b.x, b.y, b.z, b.w};
    int idx[2] = {lane * 4, 128 + lane * 4};
    #pragma unroll
    for (int h = 0; h < 2; h++)
        #pragma unroll
        for (int j = 0; j < 4; j++) {
            float v = va[h*4 + j] * scale;
            __nv_bfloat16 hi, lo;
            bf16split(v, hi, lo);
            d_xhi[(size_t)row*DD + idx[h] + j] = hi;
            d_xlo[(size_t)row*DD + idx[h] + j] = lo;
        }
}

// ============================================================
// generic transpose + split:  in [R][C] fp32 -> out [C][R] bf16 hi/lo
// ============================================================
__global__ void transpose_split_kernel(const float* __restrict__ in,
                                       __nv_bfloat16* __restrict__ outh,
                                       __nv_bfloat16* __restrict__ outl,
                                       int R, int C) {
    __shared__ float t[32][33];
    size_t boff = (size_t)blockIdx.z * R * C;
    int c0 = blockIdx.x * 32, r0 = blockIdx.y * 32;
    int tx = threadIdx.x, ty = threadIdx.y;
    #pragma unroll
    for (int i = ty; i < 32; i += 8)
        t[i][tx] = in[boff + (size_t)(r0 + i) * C + c0 + tx];
    __syncthreads();
    #pragma unroll
    for (int i = ty; i < 32; i += 8) {
        float val = t[tx][i];   // = in[r0+tx][c0+i]
        __nv_bfloat16 hi, lo;
        bf16split(val, hi, lo);
        size_t idx = boff + (size_t)(c0 + i) * R + r0 + tx;
        outh[idx] = hi;
        outl[idx] = lo;
    }
}

// ============================================================
// Epilogues
// ============================================================
struct EpiUV {
    int rowBase, colBase;
    const float *buv, *gamma, *beta;
    __device__ void operator()(int r, int c, float v0, float v1) const {
        int row = rowBase + r;
        float vv[2] = {v0, v1};
        #pragma unroll
        for (int i = 0; i < 2; i++) {
            int col = colBase + c + i;
            float val = vv[i] + buv[col];
            val = val / (1.0f + __expf(-val));
            if (col < HH) {
                d_u[(size_t)row*HH + col] = val;
            } else if (col < 2*HH) {
                d_v[(size_t)row*HH + (col - HH)] = val;
            } else {
                int s = col - 2*HH;
                float vq = val * gamma[s]      + beta[s];
                float vk = val * gamma[SS + s] + beta[SS + s];
                size_t qi = (size_t)row*SS + s;
                __nv_bfloat16 hi, lo;
                bf16split(vq, hi, lo); d_qhi[qi] = hi; d_qlo[qi] = lo;
                bf16split(vk, hi, lo); d_khi[qi] = hi; d_klo[qi] = lo;
            }
        }
    }
};

struct EpiQK {
    size_t rowOff;   // b*NN + rowBase
    int colBase;
    __device__ void operator()(int r, int c, float v0, float v1) const {
        size_t idx = (rowOff + r) * NN + colBase + c;
        float a0 = fmaxf(v0 * RSQRT_S, 0.0f); a0 *= a0;
        float a1 = fmaxf(v1 * RSQRT_S, 0.0f); a1 *= a1;
        __nv_bfloat16 h0, l0, h1, l1;
        bf16split(a0, h0, l0);
        bf16split(a1, h1, l1);
        *reinterpret_cast<__nv_bfloat162*>(d_ahi + idx) = __nv_bfloat162{h0, h1};
        *reinterpret_cast<__nv_bfloat162*>(d_alo + idx) = __nv_bfloat162{l0, l1};
    }
};

struct EpiAV {
    size_t rowOff;   // b*NN + rowBase
    int colBase;
    __device__ void operator()(int r, int c, float v0, float v1) const {
        size_t rg = rowOff + r;
        size_t idx = rg * HH + colBase + c;
        float2 uu = *reinterpret_cast<const float2*>(d_u + idx);
        float g0 = uu.x * v0, g1 = uu.y * v1;
        __nv_bfloat16 h0, l0, h1, l1;
        bf16split(g0, h0, l0);
        bf16split(g1, h1, l1);
        *reinterpret_cast<__nv_bfloat162*>(d_ghi + idx) = __nv_bfloat162{h0, h1};
        *reinterpret_cast<__nv_bfloat162*>(d_glo + idx) = __nv_bfloat162{l0, l1};
    }
};

struct EpiO {
    int rowBase, colBase;
    const float* bo;
    float* out;
    __device__ void operator()(int r, int c, float v0, float v1) const {
        int row = rowBase + r;
        int col = colBase + c;
        float2 o = {v0 + bo[col], v1 + bo[col + 1]};
        *reinterpret_cast<float2*>(out + (size_t)row*DD + col) = o;
    }
};

// ============================================================
// GEMM kernels (BN=64 grids)
// ============================================================
__global__ void __launch_bounds__(256, 2)
k_uv(const float* __restrict__ buv, const float* __restrict__ gamma,
     const float* __restrict__ beta) {
    extern __shared__ char smem[];
    int rowBase = blockIdx.y * 128, colBase = blockIdx.x * 64;
    EpiUV epi{rowBase, colBase, buv, gamma, beta};
    mma_gemm_core(d_xhi + (size_t)rowBase * DD, d_xlo + (size_t)rowBase * DD, DD,
                  d_wuvThi + (size_t)colBase * DD, d_wuvTlo + (size_t)colBase * DD, DD,
                  DD, smem, epi);
}

__global__ void __launch_bounds__(256, 2)
k_qk() {
    extern __shared__ char smem[];
    int b = blockIdx.z, rowBase = blockIdx.y * 128, colBase = blockIdx.x * 64;
    size_t ra = (size_t)b * NN + rowBase;
    size_t rb = (size_t)b * NN + colBase;
    EpiQK epi{ra, colBase};
    mma_gemm_core(d_qhi + ra * SS, d_qlo + ra * SS, SS,
                  d_khi + rb * SS, d_klo + rb * SS, SS,
                  SS, smem, epi);
}

__global__ void __launch_bounds__(256, 2)
k_av() {
    extern __shared__ char smem[];
    int b = blockIdx.z, rowBase = blockIdx.y * 128, colBase = blockIdx.x * 64;
    size_t ra = (size_t)b * NN + rowBase;
    size_t hb = (size_t)b * HH + colBase;
    EpiAV epi{ra, colBase};
    mma_gemm_core(d_ahi + ra * NN, d_alo + ra * NN, NN,
                  d_vThi + hb * NN, d_vTlo + hb * NN, NN,
                  NN, smem, epi);
}

__global__ void __launch_bounds__(256, 2)
k_o(const float* __restrict__ bo, float* __restrict__ out) {
    extern __shared__ char smem[];
    int rowBase = blockIdx.y * 128, colBase = blockIdx.x * 64;
    EpiO epi{rowBase, colBase, bo, out};
    mma_gemm_core(d_ghi + (size_t)rowBase * HH, d_glo + (size_t)rowBase * HH, HH,
                  d_woThi + (size_t)colBase * HH, d_woTlo + (size_t)colBase * HH, HH,
                  HH, smem, epi);
}

// ============================================================
extern "C" void kernel_launch(void* const* d_in, const int* in_sizes, int n_in,
                              void* d_out, int out_size) {
    (void)in_sizes; (void)n_in; (void)out_size;
    const float* x     = (const float*)d_in[0];
    const float* g     = (const float*)d_in[1];
    const float* Wuv   = (const float*)d_in[2];
    const float* buv   = (const float*)d_in[3];
    const float* gamma = (const float*)d_in[4];
    const float* beta  = (const float*)d_in[5];
    const float* Wo    = (const float*)d_in[6];
    const float* bo    = (const float*)d_in[7];
    float* out = (float*)d_out;

    static int smem_set = 0;
    if (!smem_set) {
        cudaFuncSetAttribute(k_uv, cudaFuncAttributeMaxDynamicSharedMemorySize, MMA_SMEM);
        cudaFuncSetAttribute(k_qk, cudaFuncAttributeMaxDynamicSharedMemorySize, MMA_SMEM);
        cudaFuncSetAttribute(k_av, cudaFuncAttributeMaxDynamicSharedMemorySize, MMA_SMEM);
        cudaFuncSetAttribute(k_o,  cudaFuncAttributeMaxDynamicSharedMemorySize, MMA_SMEM);
        smem_set = 1;
    }

    prep_x_kernel<<<BNROWS/8, dim3(32, 8)>>>(x, g);

    {   // W_uv: [D=256][E=1152] -> [E][D]
        __nv_bfloat16 *th, *tl;
        cudaGetSymbolAddress((void**)&th, d_wuvThi);
        cudaGetSymbolAddress((void**)&tl, d_wuvTlo);
        transpose_split_kernel<<<dim3(EE/32, DD/32, 1), dim3(32, 8)>>>(Wuv, th, tl, DD, EE);
    }
    {   // W_o: [H=512][D=256] -> [D][H]
        __nv_bfloat16 *th, *tl;
        cudaGetSymbolAddress((void**)&th, d_woThi);
        cudaGetSymbolAddress((void**)&tl, d_woTlo);
        transpose_split_kernel<<<dim3(DD/32, HH/32, 1), dim3(32, 8)>>>(Wo, th, tl, HH, DD);
    }

    k_uv<<<dim3(EE/64, BNROWS/128), 256, MMA_SMEM>>>(buv, gamma, beta);

    {   // v: per-batch [N=2048][H=512] -> [H][N]
        float* vin;
        __nv_bfloat16 *th, *tl;
        cudaGetSymbolAddress((void**)&vin, d_v);
        cudaGetSymbolAddress((void**)&th, d_vThi);
        cudaGetSymbolAddress((void**)&tl, d_vTlo);
        transpose_split_kernel<<<dim3(HH/32, NN/32, BB), dim3(32, 8)>>>(vin, th, tl, NN, HH);
    }

    k_qk<<<dim3(NN/64, NN/128, BB), 256, MMA_SMEM>>>();
    k_av<<<dim3(HH/64, NN/128, BB), 256, MMA_SMEM>>>();
    k_o<<<dim3(DD/64, BNROWS/128), 256, MMA_SMEM>>>(bo, out);
}